// round 16
// baseline (speedup 1.0000x reference)
#include <cuda_runtime.h>
#include <cuda_fp16.h>
#include <mma.h>
#include <cstdint>

using namespace nvcuda;

// ----------------------------------------------------------------------------
// out[64,14336](fp32) = (x[64,4096]*xs) @ (w[14336,4096]*ws)^T
// int32 inputs (harness promotes int8->int32), fp32 scales/output.
// R16 = R15 resubmitted (R15 bench died to container infra, not the kernel):
// R13 structure (best: 66us) with MORE WARPS/SM: 512-thread CTAs
// (16 warps, each 16feat x 32tok -> 2 accum frags, ~50 regs) -> 2 CTAs/SM
// = 32 warps/SM (vs 24). SPLITS=8 so grid 896 = 3.03 waves of 296 (1% tail).
// W = 3-stage cp.async raw int32 + convert pass; X = reg prefetch + cvt;
// scale-in-fragment + atomicAdd epilogue (exact integer adds).
// ----------------------------------------------------------------------------

#define M_TOK   64
#define KDIM    4096
#define NOUT    14336
#define TILE_N  128
#define SPLITS  8
#define KR      (KDIM / SPLITS)            // 512 per split
#define KC      32                         // K ints per iteration
#define ITERS   (KR / KC)                  // 16
#define STAGES  3
#define THREADS 512
#define RAW_ROW 144                        // bytes per raw W row (128 + 16 pad)
#define W_RAW   (TILE_N * RAW_ROW)         // 18432 per stage
#define WSTRIDE 40                         // halves per fp16 row (32 + 8 pad)
#define WSM_OFF (STAGES * W_RAW)                       // 55296
#define XSM_OFF (WSM_OFF + TILE_N * WSTRIDE * 2)       // 65536
#define SMEM_TOTAL (XSM_OFF + M_TOK * WSTRIDE * 2)     // 70656 (x2 = 141KB/SM)
#define OUT_ELEMS ((long)M_TOK * NOUT)     // 917504

__global__ void zero_kernel(float* out, long n) {
    long i = (long)blockIdx.x * blockDim.x + threadIdx.x;
    if (i < n) out[i] = 0.0f;
}

__device__ __forceinline__ uint32_t smem_u32(const void* p) {
    uint32_t a;
    asm("{ .reg .u64 t; cvta.to.shared.u64 t, %1; cvt.u32.u64 %0, t; }" : "=r"(a) : "l"(p));
    return a;
}

__device__ __forceinline__ void cp_async16(uint32_t smem_dst, const void* gmem_src) {
    asm volatile("cp.async.cg.shared.global [%0], [%1], 16;"
                 :: "r"(smem_dst), "l"(gmem_src) : "memory");
}

// 4 int32 -> 4 fp16 packed (exact for small ints)
__device__ __forceinline__ uint2 cvt4(uint4 v) {
    __half2 lo = __halves2half2(__int2half_rn((int)v.x), __int2half_rn((int)v.y));
    __half2 hi = __halves2half2(__int2half_rn((int)v.z), __int2half_rn((int)v.w));
    uint2 r;
    r.x = *reinterpret_cast<uint32_t*>(&lo);
    r.y = *reinterpret_cast<uint32_t*>(&hi);
    return r;
}

__global__ __launch_bounds__(THREADS, 2) void Model_89704686944640_kernel(
    const int* __restrict__ w, const int* __restrict__ x,
    const float* __restrict__ s0, const float* __restrict__ s1,
    float* __restrict__ out) {
    extern __shared__ char smem[];
    __half* const wsmh = reinterpret_cast<__half*>(smem + WSM_OFF);  // [128][40]
    __half* const xsmh = reinterpret_cast<__half*>(smem + XSM_OFF);  // [64][40]
    const uint32_t raw_base = smem_u32(smem);

    const int tid = threadIdx.x;
    const int wid = tid >> 5;
    const int lane = tid & 31;
    const int fg = wid & 7;                    // feature group (8 x 16)
    const int tg = wid >> 3;                   // token group (2 x 32)
    const int tile = blockIdx.x;
    const int split = blockIdx.y;
    const long wbase = (long)tile * TILE_N * KDIM;
    const int kbase0 = split * KR;

    // W: 1024 16B-chunks/iter -> 2/thr ; X: 512 -> 1/thr
    const int ch = tid & 7;
    const int ch4 = ch * 4;
    const int wrow[2] = { (tid + 0) >> 3, (tid + 512) >> 3 };
    const int xrow = tid >> 3;

    wmma::fragment<wmma::accumulator, 16, 16, 16, float> c0, c1;
    wmma::fill_fragment(c0, 0.0f);
    wmma::fill_fragment(c1, 0.0f);

    // ---- prologue ----
    uint4 xr;
    xr = *reinterpret_cast<const uint4*>(x + (long)xrow * KDIM + kbase0 + ch4);
#pragma unroll
    for (int st = 0; st < STAGES; st++) {
        const int koff = kbase0 + st * KC;
        const uint32_t sraw = raw_base + st * W_RAW;
#pragma unroll
        for (int r = 0; r < 2; r++)
            cp_async16(sraw + wrow[r] * RAW_ROW + ch * 16,
                       w + wbase + (long)wrow[r] * KDIM + koff + ch4);
        asm volatile("cp.async.commit_group;" ::: "memory");
    }

    // ---- main loop (R13 structure) ----
    for (int i = 0; i < ITERS; i++) {
        asm volatile("cp.async.wait_group %0;" :: "n"(STAGES - 1) : "memory");
        __syncthreads();   // W stage i arrived; previous tiles consumed

        const int s = i % STAGES;
        char* rawS = smem + s * W_RAW;

        // convert W raw -> fp16 tile
#pragma unroll
        for (int r = 0; r < 2; r++) {
            uint4 v = *reinterpret_cast<const uint4*>(rawS + wrow[r] * RAW_ROW + ch * 16);
            *reinterpret_cast<uint2*>(&wsmh[wrow[r] * WSTRIDE + ch4]) = cvt4(v);
        }
        // convert X regs -> fp16 tile
        *reinterpret_cast<uint2*>(&xsmh[xrow * WSTRIDE + ch4]) = cvt4(xr);
        __syncthreads();   // tiles ready; raw stage s free

        // refill: X regs for iter i+1; W stage i+3
        if (i + 1 < ITERS)
            xr = *reinterpret_cast<const uint4*>(
                x + (long)xrow * KDIM + kbase0 + (i + 1) * KC + ch4);
        if (i + STAGES < ITERS) {
            const int koff = kbase0 + (i + STAGES) * KC;
            const uint32_t sraw = raw_base + s * W_RAW;
#pragma unroll
            for (int r = 0; r < 2; r++)
                cp_async16(sraw + wrow[r] * RAW_ROW + ch * 16,
                           w + wbase + (long)wrow[r] * KDIM + koff + ch4);
        }
        asm volatile("cp.async.commit_group;" ::: "memory");

        // compute: 2 k-steps of 16; each warp: 16 feat x 32 tok
#pragma unroll
        for (int ks = 0; ks < 2; ks++) {
            wmma::fragment<wmma::matrix_b, 16, 16, 16, __half, wmma::col_major> b0;
            wmma::load_matrix_sync(b0, wsmh + (fg * 16) * WSTRIDE + ks * 16, WSTRIDE);
            wmma::fragment<wmma::matrix_a, 16, 16, 16, __half, wmma::row_major> a0, a1;
            wmma::load_matrix_sync(a0, xsmh + (tg * 32) * WSTRIDE + ks * 16, WSTRIDE);
            wmma::load_matrix_sync(a1, xsmh + (tg * 32 + 16) * WSTRIDE + ks * 16, WSTRIDE);
            wmma::mma_sync(c0, a0, b0, c0);
            wmma::mma_sync(c1, a1, b0, c1);
        }
    }

    // ---- epilogue: scale, stage per-warp, atomicAdd (exact integer adds) ----
    float sc = (s0 ? s0[0] : 1.0f) * (s1 ? s1[0] : 1.0f);
#pragma unroll
    for (int i = 0; i < c0.num_elements; i++) { c0.x[i] *= sc; c1.x[i] *= sc; }
    __syncthreads();   // done with tiles; reuse smem as fp32 scratch
    float* scr = reinterpret_cast<float*>(smem) + wid * 256;   // 1KB per warp
    const long colbase = (long)tile * TILE_N + fg * 16;
    const int er = lane >> 1;            // 0..15
    const int ec = (lane & 1) * 8;       // 0 or 8

    wmma::fragment<wmma::accumulator, 16, 16, 16, float>* frag[2] = {&c0, &c1};
#pragma unroll
    for (int f = 0; f < 2; f++) {
        wmma::store_matrix_sync(scr, *frag[f], 16, wmma::mem_row_major);
        __syncwarp();
        const long tok = tg * 32 + f * 16 + er;
        float* dst = out + tok * NOUT + colbase + ec;
#pragma unroll
        for (int j = 0; j < 8; j++)
            atomicAdd(dst + j, scr[er * 16 + ec + j]);
        __syncwarp();
    }
}

extern "C" void kernel_launch(void* const* d_in, const int* in_sizes, int n_in,
                              void* d_out, int out_size) {
    const int* w_q = nullptr;
    const int* x_q = nullptr;
    const float* s0 = nullptr;
    const float* s1 = nullptr;
    for (int i = 0; i < n_in; i++) {
        long n = in_sizes[i];
        if (n == (long)NOUT * KDIM) w_q = (const int*)d_in[i];
        else if (n == (long)M_TOK * KDIM) x_q = (const int*)d_in[i];
        else if (n <= 1) { if (!s0) s0 = (const float*)d_in[i]; else if (!s1) s1 = (const float*)d_in[i]; }
    }
    if (!x_q && n_in > 0) x_q = (const int*)d_in[0];
    if (!s0 && n_in > 1) s0 = (const float*)d_in[1];
    if (!w_q && n_in > 2) w_q = (const int*)d_in[2];
    if (!s1 && n_in > 3) s1 = (const float*)d_in[3];
    float* out = (float*)d_out;

    // zero the whole output (atomic accumulation target; graph-replay safe)
    long n = (long)out_size;
    zero_kernel<<<(int)((n + 255) / 256), 256>>>(out, n);

    cudaFuncSetAttribute(Model_89704686944640_kernel,
                         cudaFuncAttributeMaxDynamicSharedMemorySize, SMEM_TOTAL);
    dim3 grid(NOUT / TILE_N, SPLITS);
    Model_89704686944640_kernel<<<grid, THREADS, SMEM_TOTAL>>>(w_q, x_q, s0, s1, out);
}

// round 17
// speedup vs baseline: 1.2314x; 1.2314x over previous
#include <cuda_runtime.h>
#include <cuda_fp16.h>
#include <mma.h>
#include <cstdint>

using namespace nvcuda;

// ----------------------------------------------------------------------------
// out[64,14336](fp32) = (x[64,4096]*xs) @ (w[14336,4096]*ws)^T
// int32 inputs (harness promotes int8->int32), fp32 scales/output.
// R17 = R10's GEMM core (fastest observed, ~58us) with the epilogue
// overheads removed: scale-in-fragment + atomicAdd into pre-zeroed out
// (replaces 14.7MB partial scratch + 6.9us reduce kernel).
// W AND X both via 2-stage cp.async raw int32 -> convert pass -> fp16 tiles
// (no exposed sync-LDG waits). Split-K x4, 448 CTAs, 256 thr, 3 CTAs/SM.
// ----------------------------------------------------------------------------

#define M_TOK   64
#define KDIM    4096
#define NOUT    14336
#define TILE_N  128
#define SPLITS  4
#define KR      (KDIM / SPLITS)            // 1024 per split
#define KC      32                         // K ints per iteration
#define ITERS   (KR / KC)                  // 32
#define RAW_ROW 144                        // bytes per raw row (128 + 16 pad)
#define W_RAW   (TILE_N * RAW_ROW)         // 18432
#define X_RAW   (M_TOK * RAW_ROW)          // 9216
#define STAGE_BYTES (W_RAW + X_RAW)        // 27648
#define WSTRIDE 40                         // halves per fp16 row (32 + 8 pad)
#define WSM_OFF (2 * STAGE_BYTES)                       // 55296
#define XSM_OFF (WSM_OFF + TILE_N * WSTRIDE * 2)        // 65536
#define SMEM_TOTAL (XSM_OFF + M_TOK * WSTRIDE * 2)      // 70656 (x3 = 207KB/SM)
#define OUT_ELEMS ((long)M_TOK * NOUT)     // 917504

__global__ void zero_kernel(float* out, long n) {
    long i = (long)blockIdx.x * blockDim.x + threadIdx.x;
    if (i < n) out[i] = 0.0f;
}

__device__ __forceinline__ uint32_t smem_u32(const void* p) {
    uint32_t a;
    asm("{ .reg .u64 t; cvta.to.shared.u64 t, %1; cvt.u32.u64 %0, t; }" : "=r"(a) : "l"(p));
    return a;
}

__device__ __forceinline__ void cp_async16(uint32_t smem_dst, const void* gmem_src) {
    asm volatile("cp.async.cg.shared.global [%0], [%1], 16;"
                 :: "r"(smem_dst), "l"(gmem_src) : "memory");
}

// 4 int32 -> 4 fp16 packed (exact for small ints)
__device__ __forceinline__ uint2 cvt4(uint4 v) {
    __half2 lo = __halves2half2(__int2half_rn((int)v.x), __int2half_rn((int)v.y));
    __half2 hi = __halves2half2(__int2half_rn((int)v.z), __int2half_rn((int)v.w));
    uint2 r;
    r.x = *reinterpret_cast<uint32_t*>(&lo);
    r.y = *reinterpret_cast<uint32_t*>(&hi);
    return r;
}

__global__ __launch_bounds__(256, 3) void Model_89704686944640_kernel(
    const int* __restrict__ w, const int* __restrict__ x,
    const float* __restrict__ s0, const float* __restrict__ s1,
    float* __restrict__ out) {
    extern __shared__ char smem[];
    __half* const wsmh = reinterpret_cast<__half*>(smem + WSM_OFF);  // [128][40]
    __half* const xsmh = reinterpret_cast<__half*>(smem + XSM_OFF);  // [64][40]
    const uint32_t raw_base = smem_u32(smem);

    const int tid = threadIdx.x;
    const int wid = tid >> 5;
    const int lane = tid & 31;
    const int fg = wid & 3;                    // feature group (4 x 32)
    const int tg = wid >> 2;                   // token group (2 x 32)
    const int tile = blockIdx.x;
    const int split = blockIdx.y;
    const long wbase = (long)tile * TILE_N * KDIM;
    const int kbase0 = split * KR;

    wmma::fragment<wmma::accumulator, 16, 16, 16, float> c00, c01, c10, c11;
    wmma::fill_fragment(c00, 0.0f); wmma::fill_fragment(c01, 0.0f);
    wmma::fill_fragment(c10, 0.0f); wmma::fill_fragment(c11, 0.0f);

    // thread load coords: W 1024 chunks (4/thr), X 512 chunks (2/thr)
    // chunk idx -> row = idx>>3, ch = idx&7 (16B each, 8 per 128B row)
#pragma unroll
    for (int st = 0; st < 2; st++) {           // prologue: stages 0,1
        const int koff = kbase0 + st * KC;
        const uint32_t sraw = raw_base + st * STAGE_BYTES;
#pragma unroll
        for (int r = 0; r < 4; r++) {
            int idx = tid + r * 256;
            int row = idx >> 3, ch = idx & 7;
            cp_async16(sraw + row * RAW_ROW + ch * 16,
                       w + wbase + (long)row * KDIM + koff + ch * 4);
        }
#pragma unroll
        for (int r = 0; r < 2; r++) {
            int idx = tid + r * 256;
            int row = idx >> 3, ch = idx & 7;
            cp_async16(sraw + W_RAW + row * RAW_ROW + ch * 16,
                       x + (long)row * KDIM + koff + ch * 4);
        }
        asm volatile("cp.async.commit_group;" ::: "memory");
    }

    for (int i = 0; i < ITERS; i++) {
        asm volatile("cp.async.wait_group 1;" ::: "memory");
        __syncthreads();   // stage i%2 arrived; previous tiles consumed

        const int s = i & 1;
        char* rawS = smem + s * STAGE_BYTES;

        // convert raw int32 -> fp16 tiles
#pragma unroll
        for (int r = 0; r < 4; r++) {          // W: 1024 uint4 -> 4/thr
            int idx = tid + r * 256;
            int row = idx >> 3, c4 = (idx & 7) * 4;
            uint4 v = *reinterpret_cast<const uint4*>(rawS + row * RAW_ROW + (idx & 7) * 16);
            *reinterpret_cast<uint2*>(&wsmh[row * WSTRIDE + c4]) = cvt4(v);
        }
#pragma unroll
        for (int r = 0; r < 2; r++) {          // X: 512 uint4 -> 2/thr
            int idx = tid + r * 256;
            int row = idx >> 3, c4 = (idx & 7) * 4;
            uint4 v = *reinterpret_cast<const uint4*>(rawS + W_RAW + row * RAW_ROW + (idx & 7) * 16);
            *reinterpret_cast<uint2*>(&xsmh[row * WSTRIDE + c4]) = cvt4(v);
        }
        __syncthreads();   // tiles ready; raw stage s free

        if (i + 2 < ITERS) {                   // refill stage s for iter i+2
            const int koff = kbase0 + (i + 2) * KC;
            const uint32_t sraw = raw_base + s * STAGE_BYTES;
#pragma unroll
            for (int r = 0; r < 4; r++) {
                int idx = tid + r * 256;
                int row = idx >> 3, ch = idx & 7;
                cp_async16(sraw + row * RAW_ROW + ch * 16,
                           w + wbase + (long)row * KDIM + koff + ch * 4);
            }
#pragma unroll
            for (int r = 0; r < 2; r++) {
                int idx = tid + r * 256;
                int row = idx >> 3, ch = idx & 7;
                cp_async16(sraw + W_RAW + row * RAW_ROW + ch * 16,
                           x + (long)row * KDIM + koff + ch * 4);
            }
        }
        asm volatile("cp.async.commit_group;" ::: "memory");

        // compute: 2 k-steps of 16
#pragma unroll
        for (int ks = 0; ks < 2; ks++) {
            wmma::fragment<wmma::matrix_b, 16, 16, 16, __half, wmma::col_major> b0, b1;
            wmma::load_matrix_sync(b0, wsmh + (fg * 32) * WSTRIDE + ks * 16, WSTRIDE);
            wmma::load_matrix_sync(b1, wsmh + (fg * 32 + 16) * WSTRIDE + ks * 16, WSTRIDE);
            wmma::fragment<wmma::matrix_a, 16, 16, 16, __half, wmma::row_major> a0, a1;
            wmma::load_matrix_sync(a0, xsmh + (tg * 32) * WSTRIDE + ks * 16, WSTRIDE);
            wmma::load_matrix_sync(a1, xsmh + (tg * 32 + 16) * WSTRIDE + ks * 16, WSTRIDE);
            wmma::mma_sync(c00, a0, b0, c00);
            wmma::mma_sync(c01, a0, b1, c01);
            wmma::mma_sync(c10, a1, b0, c10);
            wmma::mma_sync(c11, a1, b1, c11);
        }
    }

    // ---- epilogue: scale in-fragment, stage per-warp, atomicAdd ----
    float sc = (s0 ? s0[0] : 1.0f) * (s1 ? s1[0] : 1.0f);
#pragma unroll
    for (int i = 0; i < c00.num_elements; i++) {
        c00.x[i] *= sc; c01.x[i] *= sc; c10.x[i] *= sc; c11.x[i] *= sc;
    }
    __syncthreads();   // done with tiles; reuse smem as fp32 scratch
    float* scr = reinterpret_cast<float*>(smem) + wid * 256;   // 1KB per warp
    const long colbase = (long)tile * TILE_N + fg * 32;
    const int er = lane >> 1;            // 0..15
    const int ec = (lane & 1) * 8;       // 0 or 8

    wmma::fragment<wmma::accumulator, 16, 16, 16, float>* frag[4] = {&c00, &c01, &c10, &c11};
#pragma unroll
    for (int f = 0; f < 4; f++) {
        wmma::store_matrix_sync(scr, *frag[f], 16, wmma::mem_row_major);
        __syncwarp();
        const long tok = tg * 32 + (f >> 1) * 16 + er;
        float* dst = out + tok * NOUT + colbase + (f & 1) * 16 + ec;
#pragma unroll
        for (int j = 0; j < 8; j++)
            atomicAdd(dst + j, scr[er * 16 + ec + j]);
        __syncwarp();
    }
}

extern "C" void kernel_launch(void* const* d_in, const int* in_sizes, int n_in,
                              void* d_out, int out_size) {
    const int* w_q = nullptr;
    const int* x_q = nullptr;
    const float* s0 = nullptr;
    const float* s1 = nullptr;
    for (int i = 0; i < n_in; i++) {
        long n = in_sizes[i];
        if (n == (long)NOUT * KDIM) w_q = (const int*)d_in[i];
        else if (n == (long)M_TOK * KDIM) x_q = (const int*)d_in[i];
        else if (n <= 1) { if (!s0) s0 = (const float*)d_in[i]; else if (!s1) s1 = (const float*)d_in[i]; }
    }
    if (!x_q && n_in > 0) x_q = (const int*)d_in[0];
    if (!s0 && n_in > 1) s0 = (const float*)d_in[1];
    if (!w_q && n_in > 2) w_q = (const int*)d_in[2];
    if (!s1 && n_in > 3) s1 = (const float*)d_in[3];
    float* out = (float*)d_out;

    // zero the whole output (atomic accumulation target; graph-replay safe)
    long n = (long)out_size;
    zero_kernel<<<(int)((n + 255) / 256), 256>>>(out, n);

    cudaFuncSetAttribute(Model_89704686944640_kernel,
                         cudaFuncAttributeMaxDynamicSharedMemorySize, SMEM_TOTAL);
    dim3 grid(NOUT / TILE_N, SPLITS);
    Model_89704686944640_kernel<<<grid, 256, SMEM_TOTAL>>>(w_q, x_q, s0, s1, out);
}